// round 3
// baseline (speedup 1.0000x reference)
#include <cuda_runtime.h>

// HebbianNet, fully fused (3 layers, 1 kernel, software grid barrier).
// Closed form per layer:
//   z[b,o]  = sum_i v[b,i] * W[o,i]
//   vj      = relu(z + bias[o])
//   out     = vj + r*( A*S2[b] + Bc*z + C*vj*S1[b] + D*S1[b] )
// A,Bc,C,D folded from cw1/cb1/cw2/cb2; r = RATE/batch_num;
// S1[b]=sum_i v[b,i], S2[b]=sum_i v[b,i]^2.
// Shapes: B=8, K=1024 all layers, O = 1024,1024,512.

#define B_DIM  8
#define K_DIM  1024
#define RATE_F 0.001f
#define NBLK   128
#define NTHR   256

__device__ __align__(16) float g_act1[B_DIM * K_DIM];
__device__ __align__(16) float g_act2[B_DIM * K_DIM];

// epoch-free sense-reversing grid barrier state
__device__ unsigned g_count = 0;
__device__ unsigned g_gen   = 0;

__device__ __forceinline__ void grid_bar()
{
    __syncthreads();
    if (threadIdx.x == 0) {
        __threadfence();                          // publish this block's writes
        unsigned g = __ldcv(&g_gen);              // snapshot generation BEFORE arriving
        if (atomicAdd(&g_count, 1) == NBLK - 1) {
            atomicExch(&g_count, 0);              // reset for next barrier/replay
            __threadfence();
            atomicAdd(&g_gen, 1);                 // release (wrap-safe: equality spin)
        } else {
            while (__ldcv(&g_gen) == g) __nanosleep(32);
        }
        __threadfence();                          // acquire
    }
    __syncthreads();
}

// One layer: block handles 8 output rows starting at o_base.
// Warp j: row-pair p=j&3 (rows 2p,2p+1), K-half h=j>>2.
__device__ __forceinline__ void layer_body(
    const float* __restrict__ V, const float* __restrict__ W,
    const float* __restrict__ bias, float* __restrict__ out, int O,
    float A, float Bc, float C, float D, float rr,
    float4* Vs4, float (*red)[16], float* S1s, float* S2s)
{
    const int tid  = threadIdx.x;
    const int wid  = tid >> 5;
    const int lane = tid & 31;
    const int p    = wid & 3;
    const int h    = wid >> 2;
    const int o_base = blockIdx.x * 8;

    // prefetch W slice into registers (8 independent LDG.128; L2-resident steady state)
    const float4* Wr0 = (const float4*)(W + (size_t)(o_base + 2*p    ) * K_DIM) + h*128;
    const float4* Wr1 = (const float4*)(W + (size_t)(o_base + 2*p + 1) * K_DIM) + h*128;
    float4 w0[4], w1[4];
#pragma unroll
    for (int m = 0; m < 4; ++m) {
        w0[m] = Wr0[m*32 + lane];
        w1[m] = Wr1[m*32 + lane];
    }

    // stage V via L2 (.cg — act written by other SMs; L1 may be unvisited but be safe)
    const float4* V4 = (const float4*)V;
#pragma unroll
    for (int m = 0; m < 8; ++m) {
        int i4 = tid + 256 * m;
        Vs4[i4] = __ldcg(&V4[i4]);
    }
    __syncthreads();

    // per-batch stats: warp w -> batch w
    {
        float s1 = 0.f, s2 = 0.f;
#pragma unroll
        for (int m = 0; m < 8; ++m) {
            float4 v = Vs4[wid * 256 + m * 32 + lane];
            s1 += v.x + v.y + v.z + v.w;
            s2 = fmaf(v.x, v.x, s2); s2 = fmaf(v.y, v.y, s2);
            s2 = fmaf(v.z, v.z, s2); s2 = fmaf(v.w, v.w, s2);
        }
#pragma unroll
        for (int off = 16; off > 0; off >>= 1) {
            s1 += __shfl_xor_sync(0xffffffffu, s1, off);
            s2 += __shfl_xor_sync(0xffffffffu, s2, off);
        }
        if (lane == 0) { S1s[wid] = s1; S2s[wid] = s2; }
    }

    // GEMV: 2 rows x K/2 per warp
    float acc0[B_DIM], acc1[B_DIM];
#pragma unroll
    for (int b = 0; b < B_DIM; ++b) { acc0[b] = 0.f; acc1[b] = 0.f; }

    const int kbase = h * 128;
#pragma unroll
    for (int m = 0; m < 4; ++m) {
        const float4 a0 = w0[m];
        const float4 a1 = w1[m];
#pragma unroll
        for (int b = 0; b < B_DIM; ++b) {
            float4 v = Vs4[b * 256 + kbase + m * 32 + lane];
            acc0[b] = fmaf(a0.x, v.x, acc0[b]);
            acc0[b] = fmaf(a0.y, v.y, acc0[b]);
            acc0[b] = fmaf(a0.z, v.z, acc0[b]);
            acc0[b] = fmaf(a0.w, v.w, acc0[b]);
            acc1[b] = fmaf(a1.x, v.x, acc1[b]);
            acc1[b] = fmaf(a1.y, v.y, acc1[b]);
            acc1[b] = fmaf(a1.z, v.z, acc1[b]);
            acc1[b] = fmaf(a1.w, v.w, acc1[b]);
        }
    }

#pragma unroll
    for (int off = 16; off > 0; off >>= 1) {
#pragma unroll
        for (int b = 0; b < B_DIM; ++b) {
            acc0[b] += __shfl_xor_sync(0xffffffffu, acc0[b], off);
            acc1[b] += __shfl_xor_sync(0xffffffffu, acc1[b], off);
        }
    }
    if (lane == 0) {
#pragma unroll
        for (int b = 0; b < B_DIM; ++b) {
            red[wid][b]     = acc0[b];
            red[wid][8 + b] = acc1[b];
        }
    }
    __syncthreads();

    // combine K-halves + epilogue
    if (tid < 64) {
        const int b  = tid >> 3;
        const int j  = tid & 7;
        const int pp = j >> 1;
        const int r  = j & 1;
        const int o  = o_base + j;

        float z  = red[pp][r*8 + b] + red[pp + 4][r*8 + b];
        float vj = fmaxf(z + bias[o], 0.f);
        float sh = fmaf(A, S2s[b], fmaf(Bc, z, (C * vj + D) * S1s[b]));
        out[(size_t)b * O + o] = fmaf(rr, sh, vj);
    }
}

__global__ __launch_bounds__(NTHR, 1)
void hebbian_fused_kernel(const float* __restrict__ x,
                          const float* __restrict__ W1, const float* __restrict__ b1,
                          const float* __restrict__ W2, const float* __restrict__ b2,
                          const float* __restrict__ W3, const float* __restrict__ b3,
                          const float* __restrict__ cw1, const float* __restrict__ cb1,
                          const float* __restrict__ cw2, const float* __restrict__ cb2,
                          const int*   __restrict__ bn,
                          float*       __restrict__ outp)
{
    __shared__ float4 Vs4[B_DIM * K_DIM / 4];   // 32 KB
    __shared__ float  red[8][16];
    __shared__ float  S1s[B_DIM], S2s[B_DIM];

    // fold 1x1 convs into 4 scalars (uniform, overlaps first W/V loads)
    float A = 0.f, Bc = 0.f, C = 0.f, D = 0.f;
#pragma unroll
    for (int hh = 0; hh < 8; ++hh) {
        float e = cw2[hh];
        A  = fmaf(e, cw1[3*hh + 0], A);
        Bc = fmaf(e, cw1[3*hh + 1], Bc);
        C  = fmaf(e, cw1[3*hh + 2], C);
        D  = fmaf(e, cb1[hh],       D);
    }
    D += cb2[0];
    const float rr = RATE_F / (float)bn[0];

    // layer 1: x -> act1 (O=1024, all 128 blocks)
    layer_body(x, W1, b1, g_act1, 1024, A, Bc, C, D, rr, Vs4, red, S1s, S2s);
    grid_bar();

    // layer 2: act1 -> act2 (O=1024, all 128 blocks)
    layer_body(g_act1, W2, b2, g_act2, 1024, A, Bc, C, D, rr, Vs4, red, S1s, S2s);
    grid_bar();

    // layer 3: act2 -> out (O=512, blocks 0..63)
    if (blockIdx.x < 64)
        layer_body(g_act2, W3, b3, outp, 512, A, Bc, C, D, rr, Vs4, red, S1s, S2s);
}

extern "C" void kernel_launch(void* const* d_in, const int* in_sizes, int n_in,
                              void* d_out, int out_size)
{
    (void)in_sizes; (void)n_in; (void)out_size;
    const float* x   = (const float*)d_in[0];
    const float* W1  = (const float*)d_in[1];
    const float* b1  = (const float*)d_in[2];
    const float* W2  = (const float*)d_in[3];
    const float* b2  = (const float*)d_in[4];
    const float* W3  = (const float*)d_in[5];
    const float* b3  = (const float*)d_in[6];
    const float* cw1 = (const float*)d_in[7];
    const float* cb1 = (const float*)d_in[8];
    const float* cw2 = (const float*)d_in[9];
    const float* cb2 = (const float*)d_in[10];
    const int*   bn  = (const int*)d_in[11];
    float* outp = (float*)d_out;

    hebbian_fused_kernel<<<NBLK, NTHR>>>(x, W1, b1, W2, b2, W3, b3,
                                         cw1, cb1, cw2, cb2, bn, outp);
}